// round 16
// baseline (speedup 1.0000x reference)
#include <cuda_runtime.h>
#include <stdint.h>

#define NUM_BINS 256
#define NCH 48                       // B*C = 16*3
#define NPIX (1024 * 1024)           // H*W per channel
#define N4 (NPIX / 4)                // 262144 float4/uchar4 groups per channel
#define NQ (N4 / 4)                  // 65536 per quarter-stream
#define SLICES 64                    // slices per channel (per phase)
#define THREADS 256
#define CH_THREADS (SLICES * THREADS)       // 16384
#define QITERS (NQ / CH_THREADS)            // exactly 4
#define LEAD 5                               // hist channels of lead-in (tight)
#define LEADT (LEAD * SLICES)                // 320 lead tasks
#define NTASKS (2 * NCH * SLICES)            // 6144
#define NCTA 1184                            // 148 SMs x 8 CTAs

// Scratch (device globals — allocation-free, zero-initialized at module load)
__device__ int           g_hist[NCH * NUM_BINS];
__device__ float         g_cdf[NCH * NUM_BINS];
__device__ int           g_count[NCH];     // hist slice counters
__device__ int           g_count2[NCH];    // remap slice counters
__device__ int           g_flag[NCH];      // cdf-ready flags
__device__ unsigned char g_bins[(size_t)NCH * NPIX];    // 48 MiB

__device__ __forceinline__ int quant(float v) {
    return (int)(fminf(fmaxf(v, 0.0f), 1.0f) * 255.0f); // already in [0,255]
}

// task t -> (kind, channel, slice). Hist lead of LEAD channels, then
// alternating 64-task blocks [hist c+LEAD | remap c], then remap tail.
// Total order: hist never blocks; earliest unfinished task always runs
// => progress guaranteed at any LEAD (bounded transient spins only).
__device__ __forceinline__ void decode(int t, int& kind, int& c, int& s) {
    if (t < LEADT) { kind = 0; c = t >> 6; s = t & 63; return; }
    int u = t - LEADT;
    int p = u >> 7, w = u & 127;
    if (p < NCH - LEAD) {
        if (w < SLICES) { kind = 0; c = LEAD + p; s = w; }
        else            { kind = 1; c = p;        s = w - SLICES; }
    } else {
        int idx = u - (NCH - LEAD) * 2 * SLICES;
        kind = 1; c = (NCH - LEAD) + (idx >> 6); s = idx & 63;
    }
}

// ---------------------------------------------------------------------------
__global__ void __launch_bounds__(THREADS) he_persistent(const float* __restrict__ x,
                                                         float* __restrict__ out) {
    __shared__ int   sh[8 * NUM_BINS];          // hist warp-copies (8 KB)
    __shared__ float sscan[NUM_BINS];           // scan buf / remap LUT
    __shared__ int   s_last;

    for (int t = blockIdx.x; t < NTASKS; t += NCTA) {
        int kind, c, s;
        decode(t, kind, c, s);
        __syncthreads();                        // smem reuse boundary

        if (kind == 0) {
            // ---------------- HIST slice (channel c, slice s) ----------------
            const int warp = threadIdx.x >> 5;
            int* swh = &sh[warp * NUM_BINS];

            #pragma unroll
            for (int i = threadIdx.x; i < 8 * NUM_BINS; i += THREADS) sh[i] = 0;
            __syncthreads();

            const float4* xc = reinterpret_cast<const float4*>(x + (size_t)c * NPIX);
            uchar4*       bc = reinterpret_cast<uchar4*>(g_bins + (size_t)c * NPIX);

            const int base = s * THREADS + threadIdx.x;
            #pragma unroll
            for (int k = 0; k < QITERS; k++) {
                int i = base + k * CH_THREADS;
                float4 va = xc[i];
                float4 vb = xc[i + NQ];
                float4 vc = xc[i + 2 * NQ];
                float4 vd = xc[i + 3 * NQ];

                int a0 = quant(va.x), a1 = quant(va.y), a2 = quant(va.z), a3 = quant(va.w);
                int b0 = quant(vb.x), b1 = quant(vb.y), b2 = quant(vb.z), b3 = quant(vb.w);
                int c0 = quant(vc.x), c1 = quant(vc.y), c2 = quant(vc.z), c3 = quant(vc.w);
                int d0 = quant(vd.x), d1 = quant(vd.y), d2 = quant(vd.z), d3 = quant(vd.w);

                atomicAdd(&swh[a0], 1); atomicAdd(&swh[a1], 1);
                atomicAdd(&swh[a2], 1); atomicAdd(&swh[a3], 1);
                atomicAdd(&swh[b0], 1); atomicAdd(&swh[b1], 1);
                atomicAdd(&swh[b2], 1); atomicAdd(&swh[b3], 1);
                atomicAdd(&swh[c0], 1); atomicAdd(&swh[c1], 1);
                atomicAdd(&swh[c2], 1); atomicAdd(&swh[c3], 1);
                atomicAdd(&swh[d0], 1); atomicAdd(&swh[d1], 1);
                atomicAdd(&swh[d2], 1); atomicAdd(&swh[d3], 1);

                bc[i]          = make_uchar4((unsigned char)a0, (unsigned char)a1,
                                             (unsigned char)a2, (unsigned char)a3);
                bc[i + NQ]     = make_uchar4((unsigned char)b0, (unsigned char)b1,
                                             (unsigned char)b2, (unsigned char)b3);
                bc[i + 2 * NQ] = make_uchar4((unsigned char)c0, (unsigned char)c1,
                                             (unsigned char)c2, (unsigned char)c3);
                bc[i + 3 * NQ] = make_uchar4((unsigned char)d0, (unsigned char)d1,
                                             (unsigned char)d2, (unsigned char)d3);
            }
            __syncthreads();

            {   // flush per-warp copies
                int bin = threadIdx.x;
                int sum = 0;
                #pragma unroll
                for (int w = 0; w < 8; w++) sum += sh[w * NUM_BINS + bin];
                if (sum) atomicAdd(&g_hist[c * NUM_BINS + bin], sum);
            }

            __threadfence();
            __syncthreads();
            if (threadIdx.x == 0) {
                int v = atomicAdd(&g_count[c], 1);
                s_last = (v == SLICES - 1);
            }
            __syncthreads();

            if (s_last) {
                const int tt = threadIdx.x;
                sscan[tt] = (float)__ldcg(&g_hist[c * NUM_BINS + tt]);
                __syncthreads();

                #pragma unroll
                for (int off = 1; off < NUM_BINS; off <<= 1) {
                    float v = (tt >= off) ? sscan[tt - off] : 0.0f;
                    __syncthreads();
                    sscan[tt] += v;
                    __syncthreads();
                }

                float total = sscan[NUM_BINS - 1];
                g_cdf[c * NUM_BINS + tt] = sscan[tt] / fmaxf(total, 1.0f);
                g_hist[c * NUM_BINS + tt] = 0;      // restore zero-invariant
                __threadfence();                     // release: cdf visible first
                if (tt == 0) {
                    g_count[c] = 0;                  // reset for next replay
                    atomicExch(&g_flag[c], 1);       // publish cdf-ready
                }
            }
        } else {
            // ---------------- REMAP slice (channel c, slice s) ----------------
            if (threadIdx.x == 0) {
                while (atomicAdd(&g_flag[c], 0) == 0) __nanosleep(64);
                __threadfence();                     // acquire
            }
            __syncthreads();

            sscan[threadIdx.x] = g_cdf[c * NUM_BINS + threadIdx.x];
            __syncthreads();

            const uchar4* bc = reinterpret_cast<const uchar4*>(g_bins + (size_t)c * NPIX);
            float4*       oc = reinterpret_cast<float4*>(out + (size_t)c * NPIX);

            const int base = s * THREADS + threadIdx.x;
            #pragma unroll
            for (int k = 0; k < QITERS; k++) {
                int i = base + k * CH_THREADS;
                uchar4 qa = bc[i];
                uchar4 qb = bc[i + NQ];
                uchar4 qc = bc[i + 2 * NQ];
                uchar4 qd = bc[i + 3 * NQ];

                float4 ra, rb, rc, rd;
                ra.x = sscan[qa.x]; ra.y = sscan[qa.y]; ra.z = sscan[qa.z]; ra.w = sscan[qa.w];
                rb.x = sscan[qb.x]; rb.y = sscan[qb.y]; rb.z = sscan[qb.z]; rb.w = sscan[qb.w];
                rc.x = sscan[qc.x]; rc.y = sscan[qc.y]; rc.z = sscan[qc.z]; rc.w = sscan[qc.w];
                rd.x = sscan[qd.x]; rd.y = sscan[qd.y]; rd.z = sscan[qd.z]; rd.w = sscan[qd.w];

                __stcs(&oc[i],          ra);
                __stcs(&oc[i + NQ],     rb);
                __stcs(&oc[i + 2 * NQ], rc);
                __stcs(&oc[i + 3 * NQ], rd);
            }

            __syncthreads();
            if (threadIdx.x == 0) {
                int v = atomicAdd(&g_count2[c], 1);
                if (v == SLICES - 1) {              // last remap slice: reset
                    g_count2[c] = 0;
                    atomicExch(&g_flag[c], 0);
                }
            }
        }
    }
}

// ---------------------------------------------------------------------------
extern "C" void kernel_launch(void* const* d_in, const int* in_sizes, int n_in,
                              void* d_out, int out_size) {
    const float* x   = (const float*)d_in[0];
    float*       out = (float*)d_out;

    he_persistent<<<NCTA, THREADS>>>(x, out);
}

// round 17
// speedup vs baseline: 1.0525x; 1.0525x over previous
#include <cuda_runtime.h>
#include <stdint.h>

#define NUM_BINS 256
#define NCH 48                       // B*C = 16*3
#define NCH_BUF 24                   // bins ring: 24 channels = 24 MiB (L2-resident)
#define NPIX (1024 * 1024)           // H*W per channel
#define N4 (NPIX / 4)                // 262144 float4/uchar4 groups per channel
#define NQ (N4 / 4)                  // 65536 per quarter-stream
#define SLICES 64                    // slices per channel (per phase)
#define THREADS 256
#define CH_THREADS (SLICES * THREADS)       // 16384
#define QITERS (NQ / CH_THREADS)            // exactly 4
#define LEAD 10                              // hist channels of lead-in (optimum, R15)
#define LEADT (LEAD * SLICES)                // 640 lead tasks
#define NTASKS (2 * NCH * SLICES)            // 6144
#define NCTA 1184                            // 148 SMs x 8 CTAs

// Scratch (device globals — allocation-free, zero-initialized at module load)
__device__ int           g_hist[NCH * NUM_BINS];
__device__ float         g_cdf[NCH * NUM_BINS];
__device__ int           g_count[NCH];     // hist slice counters
__device__ int           g_count2[NCH];    // remap slice counters
__device__ int           g_count3[NCH];    // flag2 consumer counters
__device__ int           g_flag[NCH];      // cdf-ready flags
__device__ int           g_flag2[NCH];     // remap-done flags (ring back-pressure)
__device__ unsigned char g_bins[(size_t)NCH_BUF * NPIX];   // 24 MiB ring

__device__ __forceinline__ int quant(float v) {
    return (int)(fminf(fmaxf(v, 0.0f), 1.0f) * 255.0f); // already in [0,255]
}

// task t -> (kind, channel, slice). Hist lead of LEAD channels, then
// alternating 64-task blocks [hist c+LEAD | remap c], then remap tail.
// Gaps: remap c starts 128*LEAD+1 = 1281 > NCTA after hist c ends (spin-free);
//       hist c starts 14 pairs = 1792 > NCTA after remap c-24 ends (spin-free).
__device__ __forceinline__ void decode(int t, int& kind, int& c, int& s) {
    if (t < LEADT) { kind = 0; c = t >> 6; s = t & 63; return; }
    int u = t - LEADT;
    int p = u >> 7, w = u & 127;
    if (p < NCH - LEAD) {
        if (w < SLICES) { kind = 0; c = LEAD + p; s = w; }
        else            { kind = 1; c = p;        s = w - SLICES; }
    } else {
        int idx = u - (NCH - LEAD) * 2 * SLICES;
        kind = 1; c = (NCH - LEAD) + (idx >> 6); s = idx & 63;
    }
}

// ---------------------------------------------------------------------------
__global__ void __launch_bounds__(THREADS) he_persistent(const float* __restrict__ x,
                                                         float* __restrict__ out) {
    __shared__ int   sh[8 * NUM_BINS];          // hist warp-copies (8 KB)
    __shared__ float sscan[NUM_BINS];           // scan buf / remap LUT
    __shared__ int   s_last;

    for (int t = blockIdx.x; t < NTASKS; t += NCTA) {
        int kind, c, s;
        decode(t, kind, c, s);
        __syncthreads();                        // smem reuse boundary

        if (kind == 0) {
            // ---------------- HIST slice (channel c, slice s) ----------------
            // Ring back-pressure: slot c%24 must be fully consumed first.
            if (c >= NCH_BUF) {
                if (threadIdx.x == 0) {
                    while (atomicAdd(&g_flag2[c - NCH_BUF], 0) == 0) __nanosleep(64);
                    __threadfence();             // acquire
                    int v = atomicAdd(&g_count3[c - NCH_BUF], 1);
                    if (v == SLICES - 1) {       // last consumer resets for replay
                        g_count3[c - NCH_BUF] = 0;
                        atomicExch(&g_flag2[c - NCH_BUF], 0);
                    }
                }
                __syncthreads();
            }

            const int warp = threadIdx.x >> 5;
            int* swh = &sh[warp * NUM_BINS];

            #pragma unroll
            for (int i = threadIdx.x; i < 8 * NUM_BINS; i += THREADS) sh[i] = 0;
            __syncthreads();

            const float4* xc = reinterpret_cast<const float4*>(x + (size_t)c * NPIX);
            uchar4* bc = reinterpret_cast<uchar4*>(g_bins + (size_t)(c % NCH_BUF) * NPIX);

            const int base = s * THREADS + threadIdx.x;
            #pragma unroll
            for (int k = 0; k < QITERS; k++) {
                int i = base + k * CH_THREADS;
                float4 va = xc[i];
                float4 vb = xc[i + NQ];
                float4 vc = xc[i + 2 * NQ];
                float4 vd = xc[i + 3 * NQ];

                int a0 = quant(va.x), a1 = quant(va.y), a2 = quant(va.z), a3 = quant(va.w);
                int b0 = quant(vb.x), b1 = quant(vb.y), b2 = quant(vb.z), b3 = quant(vb.w);
                int c0 = quant(vc.x), c1 = quant(vc.y), c2 = quant(vc.z), c3 = quant(vc.w);
                int d0 = quant(vd.x), d1 = quant(vd.y), d2 = quant(vd.z), d3 = quant(vd.w);

                atomicAdd(&swh[a0], 1); atomicAdd(&swh[a1], 1);
                atomicAdd(&swh[a2], 1); atomicAdd(&swh[a3], 1);
                atomicAdd(&swh[b0], 1); atomicAdd(&swh[b1], 1);
                atomicAdd(&swh[b2], 1); atomicAdd(&swh[b3], 1);
                atomicAdd(&swh[c0], 1); atomicAdd(&swh[c1], 1);
                atomicAdd(&swh[c2], 1); atomicAdd(&swh[c3], 1);
                atomicAdd(&swh[d0], 1); atomicAdd(&swh[d1], 1);
                atomicAdd(&swh[d2], 1); atomicAdd(&swh[d3], 1);

                bc[i]          = make_uchar4((unsigned char)a0, (unsigned char)a1,
                                             (unsigned char)a2, (unsigned char)a3);
                bc[i + NQ]     = make_uchar4((unsigned char)b0, (unsigned char)b1,
                                             (unsigned char)b2, (unsigned char)b3);
                bc[i + 2 * NQ] = make_uchar4((unsigned char)c0, (unsigned char)c1,
                                             (unsigned char)c2, (unsigned char)c3);
                bc[i + 3 * NQ] = make_uchar4((unsigned char)d0, (unsigned char)d1,
                                             (unsigned char)d2, (unsigned char)d3);
            }
            __syncthreads();

            {   // flush per-warp copies
                int bin = threadIdx.x;
                int sum = 0;
                #pragma unroll
                for (int w = 0; w < 8; w++) sum += sh[w * NUM_BINS + bin];
                if (sum) atomicAdd(&g_hist[c * NUM_BINS + bin], sum);
            }

            __threadfence();
            __syncthreads();
            if (threadIdx.x == 0) {
                int v = atomicAdd(&g_count[c], 1);
                s_last = (v == SLICES - 1);
            }
            __syncthreads();

            if (s_last) {
                const int tt = threadIdx.x;
                sscan[tt] = (float)__ldcg(&g_hist[c * NUM_BINS + tt]);
                __syncthreads();

                #pragma unroll
                for (int off = 1; off < NUM_BINS; off <<= 1) {
                    float v = (tt >= off) ? sscan[tt - off] : 0.0f;
                    __syncthreads();
                    sscan[tt] += v;
                    __syncthreads();
                }

                float total = sscan[NUM_BINS - 1];
                g_cdf[c * NUM_BINS + tt] = sscan[tt] / fmaxf(total, 1.0f);
                g_hist[c * NUM_BINS + tt] = 0;      // restore zero-invariant
                __threadfence();                     // release: cdf visible first
                if (tt == 0) {
                    g_count[c] = 0;                  // reset for next replay
                    atomicExch(&g_flag[c], 1);       // publish cdf-ready
                }
            }
        } else {
            // ---------------- REMAP slice (channel c, slice s) ----------------
            if (threadIdx.x == 0) {
                while (atomicAdd(&g_flag[c], 0) == 0) __nanosleep(64);
                __threadfence();                     // acquire
            }
            __syncthreads();

            sscan[threadIdx.x] = g_cdf[c * NUM_BINS + threadIdx.x];
            __syncthreads();

            const uchar4* bc = reinterpret_cast<const uchar4*>(
                g_bins + (size_t)(c % NCH_BUF) * NPIX);
            float4* oc = reinterpret_cast<float4*>(out + (size_t)c * NPIX);

            const int base = s * THREADS + threadIdx.x;
            #pragma unroll
            for (int k = 0; k < QITERS; k++) {
                int i = base + k * CH_THREADS;
                uchar4 qa = bc[i];
                uchar4 qb = bc[i + NQ];
                uchar4 qc = bc[i + 2 * NQ];
                uchar4 qd = bc[i + 3 * NQ];

                float4 ra, rb, rc, rd;
                ra.x = sscan[qa.x]; ra.y = sscan[qa.y]; ra.z = sscan[qa.z]; ra.w = sscan[qa.w];
                rb.x = sscan[qb.x]; rb.y = sscan[qb.y]; rb.z = sscan[qb.z]; rb.w = sscan[qb.w];
                rc.x = sscan[qc.x]; rc.y = sscan[qc.y]; rc.z = sscan[qc.z]; rc.w = sscan[qc.w];
                rd.x = sscan[qd.x]; rd.y = sscan[qd.y]; rd.z = sscan[qd.z]; rd.w = sscan[qd.w];

                __stcs(&oc[i],          ra);
                __stcs(&oc[i + NQ],     rb);
                __stcs(&oc[i + 2 * NQ], rc);
                __stcs(&oc[i + 3 * NQ], rd);
            }

            __syncthreads();
            if (threadIdx.x == 0) {
                int v = atomicAdd(&g_count2[c], 1);
                if (v == SLICES - 1) {              // last remap slice of channel c
                    g_count2[c] = 0;
                    atomicExch(&g_flag[c], 0);      // reset cdf flag for replay
                    if (c < NCH - NCH_BUF)          // release ring slot to hist c+24
                        atomicExch(&g_flag2[c], 1);
                }
            }
        }
    }
}

// ---------------------------------------------------------------------------
extern "C" void kernel_launch(void* const* d_in, const int* in_sizes, int n_in,
                              void* d_out, int out_size) {
    const float* x   = (const float*)d_in[0];
    float*       out = (float*)d_out;

    he_persistent<<<NCTA, THREADS>>>(x, out);
}